// round 14
// baseline (speedup 1.0000x reference)
#include <cuda_runtime.h>
#include <cuda_fp16.h>
#include <stdint.h>
#include <stddef.h>

#define ND 128
#define ED 32
#define OD 128
#define TE 128
#define MAXN 10000
#define MAXE 1048576
#define NSM 148

// ---------------- device scratch ----------------
__device__ float g_Pr[MAXN * OD];     // includes +b1 baked in
__device__ float g_Pc[MAXN * OD];
__device__ float g_H[MAXN * OD];      // zeroed by final kernel of PREVIOUS run
__device__ int   g_cnt[MAXN];         // zeroed by final kernel of PREVIOUS run
__device__ int   g_pos[MAXN];
__device__ int4  g_epack[MAXE];       // {row, col, perm, 0} sorted by row
__device__ __half g_ef16[MAXE * ED];  // preconverted edge features

// ---------------- edge-kernel smem ----------------
#define PITCH_EF_B 80
#define PITCH_W_B  272
#define E_W1   0                 // 32*272 = 8704
#define E_BUF  8704
#define BUF_ROWS 0
#define BUF_COLS 512
#define BUF_EF   1024            // 128*80 = 10240
#define E_BUFSZ  11264
#define E_TOTAL  (E_BUF + 2 * E_BUFSZ)   // 31232

// ---------------- precompute / final GEMM smem ----------------
#define F_AH 0
#define F_AL 34816
#define F_WH 69632
#define F_WL 104448
#define F_B2 139264
#define F_DEG 139776
#define F_TOTAL 140288

// ---------------- helpers ----------------
__device__ __forceinline__ uint32_t smem_u32(const void* p) {
    uint32_t a;
    asm("{ .reg .u64 t; cvta.to.shared.u64 t, %1; cvt.u32.u64 %0, t; }" : "=r"(a) : "l"(p));
    return a;
}
__device__ __forceinline__ void ldmx4(uint32_t* r, uint32_t addr) {
    asm volatile("ldmatrix.sync.aligned.m8n8.x4.shared.b16 {%0,%1,%2,%3}, [%4];"
                 : "=r"(r[0]), "=r"(r[1]), "=r"(r[2]), "=r"(r[3]) : "r"(addr));
}
__device__ __forceinline__ void ldmx4t(uint32_t* r, uint32_t addr) {
    asm volatile("ldmatrix.sync.aligned.m8n8.x4.trans.shared.b16 {%0,%1,%2,%3}, [%4];"
                 : "=r"(r[0]), "=r"(r[1]), "=r"(r[2]), "=r"(r[3]) : "r"(addr));
}
__device__ __forceinline__ void mma_f16(float* d, const uint32_t* a, const uint32_t* b) {
    asm volatile(
        "mma.sync.aligned.m16n8k16.row.col.f32.f16.f16.f32 "
        "{%0,%1,%2,%3},{%4,%5,%6,%7},{%8,%9},{%0,%1,%2,%3};"
        : "+f"(d[0]), "+f"(d[1]), "+f"(d[2]), "+f"(d[3])
        : "r"(a[0]), "r"(a[1]), "r"(a[2]), "r"(a[3]), "r"(b[0]), "r"(b[1]));
}
__device__ __forceinline__ uint32_t pack2h(float x0, float x1) {
    uint32_t r;
    asm("cvt.rn.f16x2.f32 %0, %1, %2;" : "=r"(r) : "f"(x1), "f"(x0));
    return r;
}
__device__ __forceinline__ void split2h(float x0, float x1, uint32_t& hi, uint32_t& lo) {
    __half h0 = __float2half_rn(x0);
    __half h1 = __float2half_rn(x1);
    hi = ((uint32_t)__half_as_ushort(h1) << 16) | __half_as_ushort(h0);
    lo = pack2h(x0 - __half2float(h0), x1 - __half2float(h1));
}

// ---------------------------------------------------------------------------
__global__ void convert_ef_kernel(const float* __restrict__ ef, long long E) {
    long long t = (long long)blockIdx.x * blockDim.x + threadIdx.x;
    if (t < E * 2) {
        const float4* src = (const float4*)(ef + t * 16);
        uint32_t hv[8];
#pragma unroll
        for (int q = 0; q < 4; q++) {
            float4 f = src[q];
            hv[2 * q]     = pack2h(f.x, f.y);
            hv[2 * q + 1] = pack2h(f.z, f.w);
        }
        uint4* dst = (uint4*)(g_ef16 + t * 16);
        dst[0] = make_uint4(hv[0], hv[1], hv[2], hv[3]);
        dst[1] = make_uint4(hv[4], hv[5], hv[6], hv[7]);
    }
}

// ---------------- counting sort by row (per-warp int64 detection) ----------
__global__ void hist_kernel(const void* __restrict__ ei, long long E) {
    long long i = (long long)blockIdx.x * blockDim.x + threadIdx.x;
    const int2* p2 = (const int2*)ei;
    // sample a high-word guaranteed inside the rows region for BOTH layouts
    long long s = (i < E) ? ((i >= E / 2) ? i - E / 2 : i) : 0;
    int tw = ((const int*)ei)[2 * s + 1];
    bool is64 = (__ballot_sync(0xFFFFFFFFu, (i < E) && (tw != 0)) == 0);
    if (is64) {
        if (i < E) {
            int r = p2[i].x;
            asm volatile("red.global.add.s32 [%0], %1;" :: "l"(&g_cnt[r]), "r"(1) : "memory");
        }
    } else {
        if (i < E / 2) {
            int2 u = p2[i];   // rows of edges 2i, 2i+1
            asm volatile("red.global.add.s32 [%0], %1;" :: "l"(&g_cnt[u.x]), "r"(1) : "memory");
            asm volatile("red.global.add.s32 [%0], %1;" :: "l"(&g_cnt[u.y]), "r"(1) : "memory");
        } else if ((E & 1) && i == E / 2) {
            int r = p2[i].x;  // last odd row word
            asm volatile("red.global.add.s32 [%0], %1;" :: "l"(&g_cnt[r]), "r"(1) : "memory");
        }
    }
}
__global__ __launch_bounds__(1024) void scan_kernel(int N) {
    __shared__ int s[10240];
    __shared__ int wsum[32];
    int tid = threadIdx.x;
    for (int i = tid; i < N; i += 1024) s[i] = g_cnt[i];
    __syncthreads();
    int per = (N + 1023) / 1024;
    int base = tid * per;
    int loc[10];
    int local = 0;
#pragma unroll
    for (int i = 0; i < 10; i++) {
        int idx = base + i;
        int v = (i < per && idx < N) ? s[idx] : 0;
        loc[i] = v;
        local += v;
    }
    int lane = tid & 31, w = tid >> 5;
    int x = local;
    for (int d = 1; d < 32; d <<= 1) {
        int y = __shfl_up_sync(0xFFFFFFFFu, x, d);
        if (lane >= d) x += y;
    }
    if (lane == 31) wsum[w] = x;
    __syncthreads();
    if (w == 0) {
        int v = wsum[lane];
        for (int d = 1; d < 32; d <<= 1) {
            int y = __shfl_up_sync(0xFFFFFFFFu, v, d);
            if (lane >= d) v += y;
        }
        wsum[lane] = v;
    }
    __syncthreads();
    int run = x - local + (w > 0 ? wsum[w - 1] : 0);
#pragma unroll
    for (int i = 0; i < 10; i++) {
        int idx = base + i;
        if (i < per && idx < N) {
            s[idx] = run;
            run += loc[i];
        }
    }
    __syncthreads();
    for (int i = tid; i < N; i += 1024) g_pos[i] = s[i];
}
// 8 edges/thread; atomics in flight before consumers; STG.128; per-warp detect.
__global__ void scatter_sort_kernel(const void* __restrict__ ei, long long E) {
    long long b = ((long long)blockIdx.x * blockDim.x + threadIdx.x) * 8;
    long long sidx = (b < E) ? ((b >= E / 2) ? b - E / 2 : b) : 0;
    int tw = ((const int*)ei)[2 * sidx + 1];
    bool is64 = (__ballot_sync(0xFFFFFFFFu, (b < E) && (tw != 0)) == 0);
    if (b >= E) return;
    int n = (E - b) >= 8 ? 8 : (int)(E - b);
    int r[8], c[8], p[8];
#pragma unroll
    for (int i = 0; i < 8; i++) {
        long long e = b + i;
        if (i < n) {
            if (is64) {
                r[i] = (int)((const long long*)ei)[e];
                c[i] = (int)((const long long*)ei)[E + e];
            } else {
                r[i] = ((const int*)ei)[e];
                c[i] = ((const int*)ei)[E + e];
            }
        }
    }
#pragma unroll
    for (int i = 0; i < 8; i++)
        if (i < n) p[i] = atomicAdd(&g_pos[r[i]], 1);
#pragma unroll
    for (int i = 0; i < 8; i++)
        if (i < n) g_epack[p[i]] = make_int4(r[i], c[i], (int)(b + i), 0);
}

// ---------------------------------------------------------------------------
// HMMA precompute: grid (nb, 2). p==0 -> Pr = h@W1a + b1 ; p==1 -> Pc = h@W1b.
// Weights split fp32->fp16 hi/lo inline while staging.
__global__ __launch_bounds__(256, 1) void precompute_P_mma_kernel(
    const float* __restrict__ h, const float* __restrict__ W1,
    const float* __restrict__ b1g, int N) {
    extern __shared__ char sm[];
    const uint32_t sb = smem_u32(sm);
    const int tid = threadIdx.x;
    const int wid = tid >> 5;
    const int lane = tid & 31;
    const int l16 = lane & 15;
    const int qrow = lane >> 2;
    const int qcol = (lane & 3) * 2;
    const int n0 = blockIdx.x * 128;
    const int p = blockIdx.y;

    {
        int row = tid >> 1, c0 = (tid & 1) * 64;
        int node = n0 + row;
        char* ph = sm + F_AH + row * PITCH_W_B + c0 * 2;
        char* pl = sm + F_AL + row * PITCH_W_B + c0 * 2;
#pragma unroll
        for (int q = 0; q < 8; q++) {
            float4 f0 = make_float4(0.f, 0.f, 0.f, 0.f), f1 = f0;
            if (node < N) {
                f0 = *(const float4*)(h + (size_t)node * ND + c0 + q * 8);
                f1 = *(const float4*)(h + (size_t)node * ND + c0 + q * 8 + 4);
            }
            uint32_t h0, l0, h1, l1, h2, l2, h3, l3;
            split2h(f0.x, f0.y, h0, l0); split2h(f0.z, f0.w, h1, l1);
            split2h(f1.x, f1.y, h2, l2); split2h(f1.z, f1.w, h3, l3);
            *(uint4*)(ph + q * 16) = make_uint4(h0, h1, h2, h3);
            *(uint4*)(pl + q * 16) = make_uint4(l0, l1, l2, l3);
        }
    }
    // stage W half (rows p*128 .. p*128+127 of W1) with inline hi/lo split
    for (int t = tid; t < 4096; t += 256) {
        int k = t >> 5, c4 = (t & 31) << 2;
        float4 w = *(const float4*)(W1 + (size_t)(p * ND + k) * OD + c4);
        uint32_t h0, l0, h1, l1;
        split2h(w.x, w.y, h0, l0);
        split2h(w.z, w.w, h1, l1);
        *(uint2*)(sm + F_WH + k * PITCH_W_B + c4 * 2) = make_uint2(h0, h1);
        *(uint2*)(sm + F_WL + k * PITCH_W_B + c4 * 2) = make_uint2(l0, l1);
    }
    __syncthreads();

    const int m0 = wid * 16;
    uint32_t ahf[8][4], alf[8][4];
    {
        uint32_t ab_h = sb + F_AH + (m0 + l16) * PITCH_W_B + (lane >> 4) * 16;
        uint32_t ab_l = sb + F_AL + (m0 + l16) * PITCH_W_B + (lane >> 4) * 16;
#pragma unroll
        for (int k = 0; k < 8; k++) {
            ldmx4(ahf[k], ab_h + k * 32);
            ldmx4(alf[k], ab_l + k * 32);
        }
    }

    float acc[16][4];
#pragma unroll
    for (int i = 0; i < 16; i++)
#pragma unroll
        for (int j = 0; j < 4; j++) acc[i][j] = 0.f;
#pragma unroll
    for (int n2 = 0; n2 < 8; n2++) {
#pragma unroll
        for (int k = 0; k < 8; k++) {
            uint32_t bh[4], bl[4];
            uint32_t ba = (k * 16 + l16) * PITCH_W_B + n2 * 32 + (lane >> 4) * 16;
            ldmx4t(bh, sb + F_WH + ba);
            ldmx4t(bl, sb + F_WL + ba);
            mma_f16(acc[2 * n2],     ahf[k], bh);
            mma_f16(acc[2 * n2],     ahf[k], bl);
            mma_f16(acc[2 * n2],     alf[k], bh);
            mma_f16(acc[2 * n2 + 1], ahf[k], bh + 2);
            mma_f16(acc[2 * n2 + 1], ahf[k], bl + 2);
            mma_f16(acc[2 * n2 + 1], alf[k], bh + 2);
        }
    }
    float* base = (p == 0) ? g_Pr : g_Pc;
    const int node_lo = n0 + m0 + qrow;
    const int node_hi = node_lo + 8;
#pragma unroll
    for (int n2 = 0; n2 < 8; n2++) {
#pragma unroll
        for (int hlf = 0; hlf < 2; hlf++) {
            int col = n2 * 16 + hlf * 8 + qcol;
            float2 b1c = make_float2(0.f, 0.f);
            if (p == 0) b1c = *(const float2*)(b1g + col);
            float* a = acc[2 * n2 + hlf];
            if (node_lo < N)
                *(float2*)(base + (size_t)node_lo * OD + col) =
                    make_float2(a[0] + b1c.x, a[1] + b1c.y);
            if (node_hi < N)
                *(float2*)(base + (size_t)node_hi * OD + col) =
                    make_float2(a[2] + b1c.x, a[3] + b1c.y);
        }
    }
}

// ---------------------------------------------------------------------------
// Edge kernel over SORTED edges (packed int4), double-buffered staging,
// warp-uniform fast path. W1c converted fp32->fp16 inline while staging.
__global__ __launch_bounds__(256, 3) void edge_hidden_kernel(
    const float* __restrict__ W1, long long E, int n_tiles) {
    extern __shared__ char sm[];
    const uint32_t sb = smem_u32(sm);
    const int tid = threadIdx.x;
    const int wid = tid >> 5;
    const int lane = tid & 31;
    const unsigned FULL = 0xFFFFFFFFu;

    for (int t = tid; t < 1024; t += 256) {
        int k = t >> 5, c4 = (t & 31) << 2;
        float4 w = *(const float4*)(W1 + (size_t)(2 * ND + k) * OD + c4);
        *(uint2*)(sm + E_W1 + k * PITCH_W_B + c4 * 2) =
            make_uint2(pack2h(w.x, w.y), pack2h(w.z, w.w));
    }

    const int m0 = wid * 16;
    const int qrow = lane >> 2;
    const int qcol = (lane & 3) * 2;
    const int l16 = lane & 15;
    const uint32_t blane_off = l16 * PITCH_W_B + (lane >> 4) * 16;

    // ---- prologue: stage first tile into buf 0 ----
    {
        const long long e00 = (long long)blockIdx.x * TE;
        if (tid < TE) {
            long long p = e00 + tid;
            int4 pk = make_int4(0, 0, 0, 0);
            if (p < E) pk = g_epack[p];
            *(int*)(sm + E_BUF + BUF_ROWS + tid * 4) = pk.x;
            *(int*)(sm + E_BUF + BUF_COLS + tid * 4) = pk.y;
        }
        {
            int er = tid >> 1, c0h = (tid & 1) * 16;
            long long p = e00 + er;
            uint4 v0 = make_uint4(0, 0, 0, 0), v1 = v0;
            if (p < E) {
                long long e = (long long)g_epack[p].z;
                const uint4* pf = (const uint4*)(g_ef16 + e * ED + c0h);
                v0 = pf[0]; v1 = pf[1];
            }
            char* ph = sm + E_BUF + BUF_EF + er * PITCH_EF_B + c0h * 2;
            *(uint4*)ph = v0;
            *(uint4*)(ph + 16) = v1;
        }
    }
    __syncthreads();

    int it = 0;
    for (int tile = blockIdx.x; tile < n_tiles; tile += gridDim.x, it++) {
        const long long e0 = (long long)tile * TE;
        const uint32_t cb = E_BUF + (uint32_t)(it & 1) * E_BUFSZ;
        const uint32_t nb2 = E_BUF + (uint32_t)((it + 1) & 1) * E_BUFSZ;
        const int ntile = tile + gridDim.x;
        const bool has_next = ntile < n_tiles;

        // ---- early-issue next tile loads ----
        int4 npk = make_int4(0, 0, 0, 0);
        uint4 nv0 = make_uint4(0, 0, 0, 0), nv1 = nv0;
        if (has_next) {
            long long e0n = (long long)ntile * TE;
            if (tid < TE) {
                long long p = e0n + tid;
                if (p < E) npk = g_epack[p];
            }
            {
                long long p = e0n + (tid >> 1);
                if (p < E) {
                    long long e = (long long)g_epack[p].z;
                    const uint4* pf = (const uint4*)(g_ef16 + e * ED + (tid & 1) * 16);
                    nv0 = pf[0]; nv1 = pf[1];
                }
            }
        }

        // ---- compute current tile ----
        int* s_rows = (int*)(sm + cb + BUF_ROWS);
        int* s_cols = (int*)(sm + cb + BUF_COLS);
        const uint32_t efA = sb + cb + BUF_EF + (m0 + l16) * PITCH_EF_B + ((lane >> 4) * 8) * 2;

        const int e_lo = m0 + qrow, e_hi = e_lo + 8;
        const int r_lo = s_rows[e_lo], r_hi = s_rows[e_hi];
        const int c_lo = s_cols[e_lo], c_hi = s_cols[e_hi];
        const bool v_lo = (e0 + e_lo) < E;
        const bool v_hi = (e0 + e_hi) < E;
        const float* prl_base = g_Pr + (size_t)r_lo * OD;
        const float* pcl_base = g_Pc + (size_t)c_lo * OD;
        const float* pch_base = g_Pc + (size_t)c_hi * OD;
        float* Hlo = g_H + (size_t)r_lo * OD;

        uint32_t eh[2][4];
        ldmx4(eh[0], efA);
        ldmx4(eh[1], efA + 32);

        int r0 = __shfl_sync(FULL, r_lo, 0);
        bool uni = __all_sync(FULL, (r_lo == r0) && (r_hi == r0));

        if (uni) {
#pragma unroll
            for (int g = 0; g < 4; g++) {
                float2 prl[4], pcl[4], pch[4];
#pragma unroll
                for (int cc = 0; cc < 4; cc++) {
                    int col = (4 * g + cc) * 8 + qcol;
                    prl[cc] = *(const float2*)(prl_base + col);
                    pcl[cc] = *(const float2*)(pcl_base + col);
                    pch[cc] = *(const float2*)(pch_base + col);
                }
#pragma unroll
                for (int t = 0; t < 2; t++) {
                    int n2 = 2 * g + t;
                    float a8[8];
#pragma unroll
                    for (int j = 0; j < 8; j++) a8[j] = 0.f;
#pragma unroll
                    for (int k = 0; k < 2; k++) {
                        uint32_t b[4];
                        ldmx4t(b, sb + E_W1 + k * 16 * PITCH_W_B + n2 * 32 + blane_off);
                        mma_f16(a8,     eh[k], b);
                        mma_f16(a8 + 4, eh[k], b + 2);
                    }
#pragma unroll
                    for (int u = 0; u < 2; u++) {
                        int cc = 2 * t + u;
                        int col = (4 * g + cc) * 8 + qcol;
                        float h0 = fmaxf(a8[u*4+0] + prl[cc].x + pcl[cc].x, 0.f);
                        float h1 = fmaxf(a8[u*4+1] + prl[cc].y + pcl[cc].y, 0.f);
                        float h2 = fmaxf(a8[u*4+2] + prl[cc].x + pch[cc].x, 0.f);
                        float h3 = fmaxf(a8[u*4+3] + prl[cc].y + pch[cc].y, 0.f);
                        if (!v_lo) { h0 = 0.f; h1 = 0.f; }
                        if (!v_hi) { h2 = 0.f; h3 = 0.f; }
                        h0 += h2; h1 += h3;
                        h0 += __shfl_down_sync(FULL, h0, 16);
                        h1 += __shfl_down_sync(FULL, h1, 16);
                        h0 += __shfl_down_sync(FULL, h0, 8);
                        h1 += __shfl_down_sync(FULL, h1, 8);
                        h0 += __shfl_down_sync(FULL, h0, 4);
                        h1 += __shfl_down_sync(FULL, h1, 4);
                        if (qrow == 0)
                            asm volatile("red.global.add.v2.f32 [%0], {%1,%2};"
                                         :: "l"(Hlo + col), "f"(h0), "f"(h1) : "memory");
                    }
                }
            }
        } else {
            const float* prh_base = g_Pr + (size_t)r_hi * OD;
            float* Hhi = g_H + (size_t)r_hi * OD;
            int rt;
            rt = __shfl_down_sync(FULL, r_lo, 4);  const bool s1l = (qrow < 7) && (rt == r_lo);
            rt = __shfl_down_sync(FULL, r_lo, 8);  const bool s2l = (qrow < 6) && (rt == r_lo);
            rt = __shfl_down_sync(FULL, r_lo, 16); const bool s4l = (qrow < 4) && (rt == r_lo);
            rt = __shfl_up_sync(FULL, r_lo, 4);    const bool hl  = (qrow == 0) || (rt != r_lo);
            rt = __shfl_down_sync(FULL, r_hi, 4);  const bool s1h = (qrow < 7) && (rt == r_hi);
            rt = __shfl_down_sync(FULL, r_hi, 8);  const bool s2h = (qrow < 6) && (rt == r_hi);
            rt = __shfl_down_sync(FULL, r_hi, 16); const bool s4h = (qrow < 4) && (rt == r_hi);
            rt = __shfl_up_sync(FULL, r_hi, 4);    const bool hh  = (qrow == 0) || (rt != r_hi);
#pragma unroll
            for (int g = 0; g < 4; g++) {
                float2 prl[4], prh[4], pcl[4], pch[4];
#pragma unroll
                for (int cc = 0; cc < 4; cc++) {
                    int col = (4 * g + cc) * 8 + qcol;
                    prl[cc] = *(const float2*)(prl_base + col);
                    prh[cc] = *(const float2*)(prh_base + col);
                    pcl[cc] = *(const float2*)(pcl_base + col);
                    pch[cc] = *(const float2*)(pch_base + col);
                }
#pragma unroll
                for (int t = 0; t < 2; t++) {
                    int n2 = 2 * g + t;
                    float a8[8];
#pragma unroll
                    for (int j = 0; j < 8; j++) a8[j] = 0.f;
#pragma unroll
                    for (int k = 0; k < 2; k++) {
                        uint32_t b[4];
                        ldmx4t(b, sb + E_W1 + k * 16 * PITCH_W_B + n2 * 32 + blane_off);
                        mma_f16(a8,     eh[k], b);
                        mma_f16(a8 + 4, eh[k], b + 2);
                    }
#pragma unroll
                    for (int u = 0; u < 2; u++) {
                        int cc = 2 * t + u;
                        int col = (4 * g + cc) * 8 + qcol;
                        float h0 = fmaxf(a8[u*4+0] + prl[cc].x + pcl[cc].x, 0.f);
                        float h1 = fmaxf(a8[u*4+1] + prl[cc].y + pcl[cc].y, 0.f);
                        float h2 = fmaxf(a8[u*4+2] + prh[cc].x + pch[cc].x, 0.f);
                        float h3 = fmaxf(a8[u*4+3] + prh[cc].y + pch[cc].y, 0.f);
                        if (!v_lo) { h0 = 0.f; h1 = 0.f; }
                        if (!v_hi) { h2 = 0.f; h3 = 0.f; }
                        float s;
                        s = __shfl_down_sync(FULL, h0, 4);  if (s1l) h0 += s;
                        s = __shfl_down_sync(FULL, h0, 8);  if (s2l) h0 += s;
                        s = __shfl_down_sync(FULL, h0, 16); if (s4l) h0 += s;
                        s = __shfl_down_sync(FULL, h1, 4);  if (s1l) h1 += s;
                        s = __shfl_down_sync(FULL, h1, 8);  if (s2l) h1 += s;
                        s = __shfl_down_sync(FULL, h1, 16); if (s4l) h1 += s;
                        s = __shfl_down_sync(FULL, h2, 4);  if (s1h) h2 += s;
                        s = __shfl_down_sync(FULL, h2, 8);  if (s2h) h2 += s;
                        s = __shfl_down_sync(FULL, h2, 16); if (s4h) h2 += s;
                        s = __shfl_down_sync(FULL, h3, 4);  if (s1h) h3 += s;
                        s = __shfl_down_sync(FULL, h3, 8);  if (s2h) h3 += s;
                        s = __shfl_down_sync(FULL, h3, 16); if (s4h) h3 += s;
                        if (hl)
                            asm volatile("red.global.add.v2.f32 [%0], {%1,%2};"
                                         :: "l"(Hlo + col), "f"(h0), "f"(h1) : "memory");
                        if (hh)
                            asm volatile("red.global.add.v2.f32 [%0], {%1,%2};"
                                         :: "l"(Hhi + col), "f"(h2), "f"(h3) : "memory");
                    }
                }
            }
        }

        // ---- store next tile into alternate buffer, single sync ----
        if (has_next) {
            if (tid < TE) {
                *(int*)(sm + nb2 + BUF_ROWS + tid * 4) = npk.x;
                *(int*)(sm + nb2 + BUF_COLS + tid * 4) = npk.y;
            }
            char* ph = sm + nb2 + BUF_EF + (tid >> 1) * PITCH_EF_B + ((tid & 1) * 16) * 2;
            *(uint4*)ph = nv0;
            *(uint4*)(ph + 16) = nv1;
        }
        __syncthreads();
    }
}

// ---------------------------------------------------------------------------
// Final: out = g_H @ W2 + deg * b2 (3-term split). SELF-CLEANING: zeroes its
// g_H node-block and g_cnt entries after staging, so the next replay starts
// from zeroed accumulators without dedicated zero kernels.
__global__ __launch_bounds__(256, 1) void final_out_mma_kernel(
    const float* __restrict__ W2, const float* __restrict__ b2g,
    float* __restrict__ out, int N) {
    extern __shared__ char sm[];
    const uint32_t sb = smem_u32(sm);
    const int tid = threadIdx.x;
    const int wid = tid >> 5;
    const int lane = tid & 31;
    const int l16 = lane & 15;
    const int qrow = lane >> 2;
    const int qcol = (lane & 3) * 2;
    const int n0 = blockIdx.x * 128;

    {
        int row = tid >> 1, c0 = (tid & 1) * 64;
        int node = n0 + row;
        char* ph = sm + F_AH + row * PITCH_W_B + c0 * 2;
        char* pl = sm + F_AL + row * PITCH_W_B + c0 * 2;
#pragma unroll
        for (int q = 0; q < 8; q++) {
            float4 f0 = make_float4(0.f, 0.f, 0.f, 0.f), f1 = f0;
            if (node < N) {
                f0 = *(const float4*)(g_H + (size_t)node * OD + c0 + q * 8);
                f1 = *(const float4*)(g_H + (size_t)node * OD + c0 + q * 8 + 4);
            }
            uint32_t h0, l0, h1, l1, h2, l2, h3, l3;
            split2h(f0.x, f0.y, h0, l0); split2h(f0.z, f0.w, h1, l1);
            split2h(f1.x, f1.y, h2, l2); split2h(f1.z, f1.w, h3, l3);
            *(uint4*)(ph + q * 16) = make_uint4(h0, h1, h2, h3);
            *(uint4*)(pl + q * 16) = make_uint4(l0, l1, l2, l3);
        }
    }
    for (int t = tid; t < 4096; t += 256) {
        int k = t >> 5, c4 = (t & 31) << 2;
        float4 w = *(const float4*)(W2 + (size_t)k * OD + c4);
        uint32_t h0, l0, h1, l1;
        split2h(w.x, w.y, h0, l0);
        split2h(w.z, w.w, h1, l1);
        *(uint2*)(sm + F_WH + k * PITCH_W_B + c4 * 2) = make_uint2(h0, h1);
        *(uint2*)(sm + F_WL + k * PITCH_W_B + c4 * 2) = make_uint2(l0, l1);
    }
    if (tid < 128) {
        int node = n0 + tid;
        ((float*)(sm + F_B2))[tid] = b2g[tid];
        ((float*)(sm + F_DEG))[tid] = (node < N) ? (float)g_cnt[node] : 0.f;
    }
    __syncthreads();

    // self-clean: zero this block's g_H rows and g_cnt entries (disjoint
    // across blocks; smem copies already hold the values we need).
    {
        int row = tid >> 1, c0 = (tid & 1) * 64;
        int node = n0 + row;
        if (node < N) {
            float4 z = make_float4(0.f, 0.f, 0.f, 0.f);
#pragma unroll
            for (int q = 0; q < 16; q++)
                *(float4*)(g_H + (size_t)node * OD + c0 + q * 4) = z;
        }
        if (tid < 128 && (n0 + tid) < N) g_cnt[n0 + tid] = 0;
    }

    const int m0 = wid * 16;
    uint32_t ahf[8][4], alf[8][4];
    {
        uint32_t ab_h = sb + F_AH + (m0 + l16) * PITCH_W_B + (lane >> 4) * 16;
        uint32_t ab_l = sb + F_AL + (m0 + l16) * PITCH_W_B + (lane >> 4) * 16;
#pragma unroll
        for (int k = 0; k < 8; k++) {
            ldmx4(ahf[k], ab_h + k * 32);
            ldmx4(alf[k], ab_l + k * 32);
        }
    }

    float acc[16][4];
#pragma unroll
    for (int i = 0; i < 16; i++)
#pragma unroll
        for (int j = 0; j < 4; j++) acc[i][j] = 0.f;
#pragma unroll
    for (int n2 = 0; n2 < 8; n2++) {
#pragma unroll
        for (int k = 0; k < 8; k++) {
            uint32_t bh[4], bl[4];
            uint32_t ba = (k * 16 + l16) * PITCH_W_B + n2 * 32 + (lane >> 4) * 16;
            ldmx4t(bh, sb + F_WH + ba);
            ldmx4t(bl, sb + F_WL + ba);
            mma_f16(acc[2 * n2],     ahf[k], bh);
            mma_f16(acc[2 * n2],     ahf[k], bl);
            mma_f16(acc[2 * n2],     alf[k], bh);
            mma_f16(acc[2 * n2 + 1], ahf[k], bh + 2);
            mma_f16(acc[2 * n2 + 1], ahf[k], bl + 2);
            mma_f16(acc[2 * n2 + 1], alf[k], bh + 2);
        }
    }

    const int node_lo = n0 + m0 + qrow;
    const int node_hi = node_lo + 8;
    const float deg_lo = ((float*)(sm + F_DEG))[m0 + qrow];
    const float deg_hi = ((float*)(sm + F_DEG))[m0 + qrow + 8];
#pragma unroll
    for (int n2 = 0; n2 < 8; n2++) {
#pragma unroll
        for (int hlf = 0; hlf < 2; hlf++) {
            int col = n2 * 16 + hlf * 8 + qcol;
            float2 b2c = *(const float2*)(sm + F_B2 + col * 4);
            float* a = acc[2 * n2 + hlf];
            if (node_lo < N)
                *(float2*)(out + (size_t)node_lo * OD + col) =
                    make_float2(a[0] + deg_lo * b2c.x, a[1] + deg_lo * b2c.y);
            if (node_hi < N)
                *(float2*)(out + (size_t)node_hi * OD + col) =
                    make_float2(a[2] + deg_hi * b2c.x, a[3] + deg_hi * b2c.y);
        }
    }
}

// ---------------------------------------------------------------------------
extern "C" void kernel_launch(void* const* d_in, const int* in_sizes, int n_in,
                              void* d_out, int out_size) {
    const float* h = (const float*)d_in[0];
    const void* edge_index = d_in[1];
    const float* ef = (const float*)d_in[2];
    const float *W1 = 0, *b1 = 0, *W2 = 0, *b2 = 0;
    for (int i = 3; i < n_in; i++) {
        int s = in_sizes[i];
        if (s == (2 * ND + ED) * OD) W1 = (const float*)d_in[i];
        else if (s == OD * OD) W2 = (const float*)d_in[i];
        else if (s == OD) { if (!b1) b1 = (const float*)d_in[i]; else b2 = (const float*)d_in[i]; }
    }
    if (!W1 || !b1 || !W2 || !b2) return;

    int N = in_sizes[0] / ND;
    if (N > MAXN) N = MAXN;
    long long E = (long long)(in_sizes[1] / 2);
    if (E > MAXE) E = MAXE;
    float* out = (float*)d_out;
    int n_tiles = (int)((E + TE - 1) / TE);
    int nb = (N + 127) / 128;

    static cudaStream_t s1 = 0, s2 = 0;
    static cudaEvent_t e0 = 0, e1 = 0, e2 = 0;
    if (!s1) {
        cudaStreamCreateWithFlags(&s1, cudaStreamNonBlocking);
        cudaStreamCreateWithFlags(&s2, cudaStreamNonBlocking);
        cudaEventCreateWithFlags(&e0, cudaEventDisableTiming);
        cudaEventCreateWithFlags(&e1, cudaEventDisableTiming);
        cudaEventCreateWithFlags(&e2, cudaEventDisableTiming);
    }

    // fork
    cudaEventRecord(e0, 0);
    cudaStreamWaitEvent(s1, e0, 0);
    cudaStreamWaitEvent(s2, e0, 0);

    // chain A (default): counting sort (g_cnt pre-zeroed by previous run)
    hist_kernel<<<(int)((E + 255) / 256), 256>>>(edge_index, E);
    scan_kernel<<<1, 1024>>>(N);
    scatter_sort_kernel<<<(int)((E + 2047) / 2048), 256>>>(edge_index, E);

    // chain B (s1): P precompute (weights split inline; +b1 baked into Pr)
    cudaFuncSetAttribute(precompute_P_mma_kernel,
                         cudaFuncAttributeMaxDynamicSharedMemorySize, F_TOTAL);
    {
        dim3 pgrid(nb, 2);
        precompute_P_mma_kernel<<<pgrid, 256, F_TOTAL, s1>>>(h, W1, b1, N);
    }
    cudaEventRecord(e1, s1);

    // chain C (s2): ef fp16 preconvert (g_H pre-zeroed by previous run)
    convert_ef_kernel<<<(int)((E * 2 + 255) / 256), 256, 0, s2>>>(ef, E);
    cudaEventRecord(e2, s2);

    // join
    cudaStreamWaitEvent(0, e1, 0);
    cudaStreamWaitEvent(0, e2, 0);

    int egrid = 3 * NSM;
    if (egrid > n_tiles) egrid = n_tiles;
    edge_hidden_kernel<<<egrid, 256, E_TOTAL>>>(W1, E, n_tiles);

    cudaFuncSetAttribute(final_out_mma_kernel,
                         cudaFuncAttributeMaxDynamicSharedMemorySize, F_TOTAL);
    final_out_mma_kernel<<<nb, 256, F_TOTAL>>>(W2, b2, out, N);
}

// round 15
// speedup vs baseline: 1.0481x; 1.0481x over previous
#include <cuda_runtime.h>
#include <cuda_fp16.h>
#include <stdint.h>
#include <stddef.h>

#define ND 128
#define ED 32
#define OD 128
#define TE 128
#define MAXN 10000
#define MAXE 1048576
#define NSM 148

// ---------------- device scratch ----------------
__device__ float g_Pr[MAXN * OD];     // includes +b1 baked in
__device__ float g_Pc[MAXN * OD];
__device__ float g_H[MAXN * OD];
__device__ int   g_cnt[MAXN];
__device__ int   g_pos[MAXN];
__device__ int4  g_epack[MAXE];       // {row, col, perm, 0} sorted by row
__device__ int   g_idx64;
__device__ __half g_ef16[MAXE * ED];  // preconverted edge features
__device__ __half g_W1ch[ED * OD];
__device__ __half g_Wab_hi[ND * 256];
__device__ __half g_Wab_lo[ND * 256];
__device__ __half g_W2_hi[OD * OD];
__device__ __half g_W2_lo[OD * OD];

// ---------------- edge-kernel smem ----------------
#define PITCH_EF_B 80
#define PITCH_W_B  272
#define E_W1   0                 // 32*272 = 8704
#define E_BUF  8704
#define BUF_ROWS 0
#define BUF_COLS 512
#define BUF_EF   1024            // 128*80 = 10240
#define E_BUFSZ  11264
#define E_TOTAL  (E_BUF + 2 * E_BUFSZ)   // 31232

// ---------------- precompute GEMM smem (128-node blocks) ----------------
#define F_AH 0
#define F_AL 34816
#define F_WH 69632
#define F_WL 104448
#define F_B2 139264
#define F_DEG 139776
#define F_TOTAL 140288

// ---------------- final GEMM smem (64-node blocks) ----------------
#define G_AH 0                    // 64*272 = 17408
#define G_AL 17408
#define G_WH 34816                // 128*272 = 34816
#define G_WL 69632
#define G_B2 104448               // float[128]
#define G_DEG 104960              // float[64]
#define G_TOTAL 105216

// ---------------- helpers ----------------
__device__ __forceinline__ uint32_t smem_u32(const void* p) {
    uint32_t a;
    asm("{ .reg .u64 t; cvta.to.shared.u64 t, %1; cvt.u32.u64 %0, t; }" : "=r"(a) : "l"(p));
    return a;
}
__device__ __forceinline__ void ldmx4(uint32_t* r, uint32_t addr) {
    asm volatile("ldmatrix.sync.aligned.m8n8.x4.shared.b16 {%0,%1,%2,%3}, [%4];"
                 : "=r"(r[0]), "=r"(r[1]), "=r"(r[2]), "=r"(r[3]) : "r"(addr));
}
__device__ __forceinline__ void ldmx4t(uint32_t* r, uint32_t addr) {
    asm volatile("ldmatrix.sync.aligned.m8n8.x4.trans.shared.b16 {%0,%1,%2,%3}, [%4];"
                 : "=r"(r[0]), "=r"(r[1]), "=r"(r[2]), "=r"(r[3]) : "r"(addr));
}
__device__ __forceinline__ void mma_f16(float* d, const uint32_t* a, const uint32_t* b) {
    asm volatile(
        "mma.sync.aligned.m16n8k16.row.col.f32.f16.f16.f32 "
        "{%0,%1,%2,%3},{%4,%5,%6,%7},{%8,%9},{%0,%1,%2,%3};"
        : "+f"(d[0]), "+f"(d[1]), "+f"(d[2]), "+f"(d[3])
        : "r"(a[0]), "r"(a[1]), "r"(a[2]), "r"(a[3]), "r"(b[0]), "r"(b[1]));
}
__device__ __forceinline__ uint32_t pack2h(float x0, float x1) {
    uint32_t r;
    asm("cvt.rn.f16x2.f32 %0, %1, %2;" : "=r"(r) : "f"(x1), "f"(x0));
    return r;
}
__device__ __forceinline__ void split2h(float x0, float x1, uint32_t& hi, uint32_t& lo) {
    __half h0 = __float2half_rn(x0);
    __half h1 = __float2half_rn(x1);
    hi = ((uint32_t)__half_as_ushort(h1) << 16) | __half_as_ushort(h0);
    lo = pack2h(x0 - __half2float(h0), x1 - __half2float(h1));
}

// ---------------------------------------------------------------------------
__global__ void zero_detect_kernel(const int* __restrict__ ei, int N) {
    int i = blockIdx.x * blockDim.x + threadIdx.x;
    if (i < N) g_cnt[i] = 0;
    if (blockIdx.x == 0 && threadIdx.x == 0) {
        int nz = 0;
        for (int q = 0; q < 64; q++)
            if (ei[2 * q + 1] != 0) nz++;
        g_idx64 = (nz == 0) ? 1 : 0;
    }
}
__global__ void zero_H_kernel(int nH) {
    int i = blockIdx.x * blockDim.x + threadIdx.x;
    if (i < nH) g_H[i] = 0.0f;
}
__global__ void convert_ef_kernel(const float* __restrict__ ef, long long E) {
    long long t = (long long)blockIdx.x * blockDim.x + threadIdx.x;
    if (t < E * 2) {
        const float4* src = (const float4*)(ef + t * 16);
        uint32_t hv[8];
#pragma unroll
        for (int q = 0; q < 4; q++) {
            float4 f = src[q];
            hv[2 * q]     = pack2h(f.x, f.y);
            hv[2 * q + 1] = pack2h(f.z, f.w);
        }
        uint4* dst = (uint4*)(g_ef16 + t * 16);
        dst[0] = make_uint4(hv[0], hv[1], hv[2], hv[3]);
        dst[1] = make_uint4(hv[4], hv[5], hv[6], hv[7]);
    }
}
__global__ void prep_weights_kernel(const float* __restrict__ W1, const float* __restrict__ W2) {
    int t = blockIdx.x * blockDim.x + threadIdx.x;
    if (t < OD * OD) {
        float x = W2[t];
        __half hh = __float2half_rn(x);
        g_W2_hi[t] = hh;
        g_W2_lo[t] = __float2half_rn(x - __half2float(hh));
    }
    if (t < ED * OD) g_W1ch[t] = __float2half_rn(W1[(size_t)(2 * ND) * OD + t]);
    if (t < ND * 256) {
        int k = t >> 8, n = t & 255;
        float x = (n < 128) ? W1[(size_t)k * OD + n] : W1[(size_t)(ND + k) * OD + (n - 128)];
        __half hh = __float2half_rn(x);
        g_Wab_hi[t] = hh;
        g_Wab_lo[t] = __float2half_rn(x - __half2float(hh));
    }
}

// ---------------- counting sort by row ----------------
__global__ void hist_kernel(const void* __restrict__ ei, long long E) {
    long long e = (long long)blockIdx.x * blockDim.x + threadIdx.x;
    if (e < E) {
        int r = g_idx64 ? (int)((const long long*)ei)[e] : ((const int*)ei)[e];
        asm volatile("red.global.add.s32 [%0], %1;" :: "l"(&g_cnt[r]), "r"(1) : "memory");
    }
}
__global__ __launch_bounds__(1024) void scan_kernel(int N) {
    __shared__ int s[10240];
    __shared__ int wsum[32];
    int tid = threadIdx.x;
    for (int i = tid; i < N; i += 1024) s[i] = g_cnt[i];
    __syncthreads();
    int per = (N + 1023) / 1024;
    int base = tid * per;
    int loc[10];
    int local = 0;
#pragma unroll
    for (int i = 0; i < 10; i++) {
        int idx = base + i;
        int v = (i < per && idx < N) ? s[idx] : 0;
        loc[i] = v;
        local += v;
    }
    int lane = tid & 31, w = tid >> 5;
    int x = local;
    for (int d = 1; d < 32; d <<= 1) {
        int y = __shfl_up_sync(0xFFFFFFFFu, x, d);
        if (lane >= d) x += y;
    }
    if (lane == 31) wsum[w] = x;
    __syncthreads();
    if (w == 0) {
        int v = wsum[lane];
        for (int d = 1; d < 32; d <<= 1) {
            int y = __shfl_up_sync(0xFFFFFFFFu, v, d);
            if (lane >= d) v += y;
        }
        wsum[lane] = v;
    }
    __syncthreads();
    int run = x - local + (w > 0 ? wsum[w - 1] : 0);
#pragma unroll
    for (int i = 0; i < 10; i++) {
        int idx = base + i;
        if (i < per && idx < N) {
            s[idx] = run;
            run += loc[i];
        }
    }
    __syncthreads();
    for (int i = tid; i < N; i += 1024) g_pos[i] = s[i];
}
// 8 edges/thread; atomics in flight before consumers (MLP=8); STG.128.
__global__ void scatter_sort_kernel(const void* __restrict__ ei, long long E) {
    long long b = ((long long)blockIdx.x * blockDim.x + threadIdx.x) * 8;
    if (b >= E) return;
    int n = (E - b) >= 8 ? 8 : (int)(E - b);
    const int is64 = g_idx64;
    int r[8], c[8], p[8];
#pragma unroll
    for (int i = 0; i < 8; i++) {
        long long e = b + i;
        if (i < n) {
            if (is64) {
                r[i] = (int)((const long long*)ei)[e];
                c[i] = (int)((const long long*)ei)[E + e];
            } else {
                r[i] = ((const int*)ei)[e];
                c[i] = ((const int*)ei)[E + e];
            }
        }
    }
#pragma unroll
    for (int i = 0; i < 8; i++)
        if (i < n) p[i] = atomicAdd(&g_pos[r[i]], 1);
#pragma unroll
    for (int i = 0; i < 8; i++)
        if (i < n) g_epack[p[i]] = make_int4(r[i], c[i], (int)(b + i), 0);
}

// ---------------------------------------------------------------------------
// HMMA precompute: grid (nb, 2). p==0 -> Pr = h@W1a + b1 ; p==1 -> Pc = h@W1b.
__global__ __launch_bounds__(256, 1) void precompute_P_mma_kernel(
    const float* __restrict__ h, const float* __restrict__ b1g, int N) {
    extern __shared__ char sm[];
    const uint32_t sb = smem_u32(sm);
    const int tid = threadIdx.x;
    const int wid = tid >> 5;
    const int lane = tid & 31;
    const int l16 = lane & 15;
    const int qrow = lane >> 2;
    const int qcol = (lane & 3) * 2;
    const int n0 = blockIdx.x * 128;
    const int p = blockIdx.y;

    {
        int row = tid >> 1, c0 = (tid & 1) * 64;
        int node = n0 + row;
        char* ph = sm + F_AH + row * PITCH_W_B + c0 * 2;
        char* pl = sm + F_AL + row * PITCH_W_B + c0 * 2;
#pragma unroll
        for (int q = 0; q < 8; q++) {
            float4 f0 = make_float4(0.f, 0.f, 0.f, 0.f), f1 = f0;
            if (node < N) {
                f0 = *(const float4*)(h + (size_t)node * ND + c0 + q * 8);
                f1 = *(const float4*)(h + (size_t)node * ND + c0 + q * 8 + 4);
            }
            uint32_t h0, l0, h1, l1, h2, l2, h3, l3;
            split2h(f0.x, f0.y, h0, l0); split2h(f0.z, f0.w, h1, l1);
            split2h(f1.x, f1.y, h2, l2); split2h(f1.z, f1.w, h3, l3);
            *(uint4*)(ph + q * 16) = make_uint4(h0, h1, h2, h3);
            *(uint4*)(pl + q * 16) = make_uint4(l0, l1, l2, l3);
        }
    }
    for (int t = tid; t < 2048; t += 256) {
        int k = t >> 4, c8 = (t & 15) << 3;
        *(uint4*)(sm + F_WH + k * PITCH_W_B + c8 * 2) =
            *(const uint4*)(g_Wab_hi + k * 256 + p * 128 + c8);
        *(uint4*)(sm + F_WL + k * PITCH_W_B + c8 * 2) =
            *(const uint4*)(g_Wab_lo + k * 256 + p * 128 + c8);
    }
    __syncthreads();

    const int m0 = wid * 16;
    uint32_t ahf[8][4], alf[8][4];
    {
        uint32_t ab_h = sb + F_AH + (m0 + l16) * PITCH_W_B + (lane >> 4) * 16;
        uint32_t ab_l = sb + F_AL + (m0 + l16) * PITCH_W_B + (lane >> 4) * 16;
#pragma unroll
        for (int k = 0; k < 8; k++) {
            ldmx4(ahf[k], ab_h + k * 32);
            ldmx4(alf[k], ab_l + k * 32);
        }
    }

    float acc[16][4];
#pragma unroll
    for (int i = 0; i < 16; i++)
#pragma unroll
        for (int j = 0; j < 4; j++) acc[i][j] = 0.f;
#pragma unroll
    for (int n2 = 0; n2 < 8; n2++) {
#pragma unroll
        for (int k = 0; k < 8; k++) {
            uint32_t bh[4], bl[4];
            uint32_t ba = (k * 16 + l16) * PITCH_W_B + n2 * 32 + (lane >> 4) * 16;
            ldmx4t(bh, sb + F_WH + ba);
            ldmx4t(bl, sb + F_WL + ba);
            mma_f16(acc[2 * n2],     ahf[k], bh);
            mma_f16(acc[2 * n2],     ahf[k], bl);
            mma_f16(acc[2 * n2],     alf[k], bh);
            mma_f16(acc[2 * n2 + 1], ahf[k], bh + 2);
            mma_f16(acc[2 * n2 + 1], ahf[k], bl + 2);
            mma_f16(acc[2 * n2 + 1], alf[k], bh + 2);
        }
    }
    float* base = (p == 0) ? g_Pr : g_Pc;
    const int node_lo = n0 + m0 + qrow;
    const int node_hi = node_lo + 8;
#pragma unroll
    for (int n2 = 0; n2 < 8; n2++) {
#pragma unroll
        for (int hlf = 0; hlf < 2; hlf++) {
            int col = n2 * 16 + hlf * 8 + qcol;
            float2 b1c = make_float2(0.f, 0.f);
            if (p == 0) b1c = *(const float2*)(b1g + col);
            float* a = acc[2 * n2 + hlf];
            if (node_lo < N)
                *(float2*)(base + (size_t)node_lo * OD + col) =
                    make_float2(a[0] + b1c.x, a[1] + b1c.y);
            if (node_hi < N)
                *(float2*)(base + (size_t)node_hi * OD + col) =
                    make_float2(a[2] + b1c.x, a[3] + b1c.y);
        }
    }
}

// ---------------------------------------------------------------------------
// Edge kernel over SORTED edges (packed int4), double-buffered staging,
// warp-uniform fast path (all 16 edges same destination row).
__global__ __launch_bounds__(256, 3) void edge_hidden_kernel(
    long long E, int n_tiles) {
    extern __shared__ char sm[];
    const uint32_t sb = smem_u32(sm);
    const int tid = threadIdx.x;
    const int wid = tid >> 5;
    const int lane = tid & 31;
    const unsigned FULL = 0xFFFFFFFFu;

    for (int t = tid; t < 512; t += 256) {
        int k = t >> 4, n8 = (t & 15) << 3;
        *(uint4*)(sm + E_W1 + k * PITCH_W_B + n8 * 2) = *(const uint4*)(g_W1ch + k * OD + n8);
    }

    const int m0 = wid * 16;
    const int qrow = lane >> 2;
    const int qcol = (lane & 3) * 2;
    const int l16 = lane & 15;
    const uint32_t blane_off = l16 * PITCH_W_B + (lane >> 4) * 16;

    // ---- prologue: stage first tile into buf 0 ----
    {
        const long long e00 = (long long)blockIdx.x * TE;
        if (tid < TE) {
            long long p = e00 + tid;
            int4 pk = make_int4(0, 0, 0, 0);
            if (p < E) pk = g_epack[p];
            *(int*)(sm + E_BUF + BUF_ROWS + tid * 4) = pk.x;
            *(int*)(sm + E_BUF + BUF_COLS + tid * 4) = pk.y;
        }
        {
            int er = tid >> 1, c0h = (tid & 1) * 16;
            long long p = e00 + er;
            uint4 v0 = make_uint4(0, 0, 0, 0), v1 = v0;
            if (p < E) {
                long long e = (long long)g_epack[p].z;
                const uint4* pf = (const uint4*)(g_ef16 + e * ED + c0h);
                v0 = pf[0]; v1 = pf[1];
            }
            char* ph = sm + E_BUF + BUF_EF + er * PITCH_EF_B + c0h * 2;
            *(uint4*)ph = v0;
            *(uint4*)(ph + 16) = v1;
        }
    }
    __syncthreads();

    int it = 0;
    for (int tile = blockIdx.x; tile < n_tiles; tile += gridDim.x, it++) {
        const long long e0 = (long long)tile * TE;
        const uint32_t cb = E_BUF + (uint32_t)(it & 1) * E_BUFSZ;
        const uint32_t nb2 = E_BUF + (uint32_t)((it + 1) & 1) * E_BUFSZ;
        const int ntile = tile + gridDim.x;
        const bool has_next = ntile < n_tiles;

        // ---- early-issue next tile loads ----
        int4 npk = make_int4(0, 0, 0, 0);
        uint4 nv0 = make_uint4(0, 0, 0, 0), nv1 = nv0;
        if (has_next) {
            long long e0n = (long long)ntile * TE;
            if (tid < TE) {
                long long p = e0n + tid;
                if (p < E) npk = g_epack[p];
            }
            {
                long long p = e0n + (tid >> 1);
                if (p < E) {
                    long long e = (long long)g_epack[p].z;
                    const uint4* pf = (const uint4*)(g_ef16 + e * ED + (tid & 1) * 16);
                    nv0 = pf[0]; nv1 = pf[1];
                }
            }
        }

        // ---- compute current tile ----
        int* s_rows = (int*)(sm + cb + BUF_ROWS);
        int* s_cols = (int*)(sm + cb + BUF_COLS);
        const uint32_t efA = sb + cb + BUF_EF + (m0 + l16) * PITCH_EF_B + ((lane >> 4) * 8) * 2;

        const int e_lo = m0 + qrow, e_hi = e_lo + 8;
        const int r_lo = s_rows[e_lo], r_hi = s_rows[e_hi];
        const int c_lo = s_cols[e_lo], c_hi = s_cols[e_hi];
        const bool v_lo = (e0 + e_lo) < E;
        const bool v_hi = (e0 + e_hi) < E;
        const float* prl_base = g_Pr + (size_t)r_lo * OD;
        const float* pcl_base = g_Pc + (size_t)c_lo * OD;
        const float* pch_base = g_Pc + (size_t)c_hi * OD;
        float* Hlo = g_H + (size_t)r_lo * OD;

        uint32_t eh[2][4];
        ldmx4(eh[0], efA);
        ldmx4(eh[1], efA + 32);

        int r0 = __shfl_sync(FULL, r_lo, 0);
        bool uni = __all_sync(FULL, (r_lo == r0) && (r_hi == r0));

        if (uni) {
#pragma unroll
            for (int g = 0; g < 4; g++) {
                float2 prl[4], pcl[4], pch[4];
#pragma unroll
                for (int cc = 0; cc < 4; cc++) {
                    int col = (4 * g + cc) * 8 + qcol;
                    prl[cc] = *(const float2*)(prl_base + col);
                    pcl[cc] = *(const float2*)(pcl_base + col);
                    pch[cc] = *(const float2*)(pch_base + col);
                }
#pragma unroll
                for (int t = 0; t < 2; t++) {
                    int n2 = 2 * g + t;
                    float a8[8];
#pragma unroll
                    for (int j = 0; j < 8; j++) a8[j] = 0.f;
#pragma unroll
                    for (int k = 0; k < 2; k++) {
                        uint32_t b[4];
                        ldmx4t(b, sb + E_W1 + k * 16 * PITCH_W_B + n2 * 32 + blane_off);
                        mma_f16(a8,     eh[k], b);
                        mma_f16(a8 + 4, eh[k], b + 2);
                    }
#pragma unroll
                    for (int u = 0; u < 2; u++) {
                        int cc = 2 * t + u;
                        int col = (4 * g + cc) * 8 + qcol;
                        float h0 = fmaxf(a8[u*4+0] + prl[cc].x + pcl[cc].x, 0.f);
                        float h1 = fmaxf(a8[u*4+1] + prl[cc].y + pcl[cc].y, 0.f);
                        float h2 = fmaxf(a8[u*4+2] + prl[cc].x + pch[cc].x, 0.f);
                        float h3 = fmaxf(a8[u*4+3] + prl[cc].y + pch[cc].y, 0.f);
                        if (!v_lo) { h0 = 0.f; h1 = 0.f; }
                        if (!v_hi) { h2 = 0.f; h3 = 0.f; }
                        h0 += h2; h1 += h3;
                        h0 += __shfl_down_sync(FULL, h0, 16);
                        h1 += __shfl_down_sync(FULL, h1, 16);
                        h0 += __shfl_down_sync(FULL, h0, 8);
                        h1 += __shfl_down_sync(FULL, h1, 8);
                        h0 += __shfl_down_sync(FULL, h0, 4);
                        h1 += __shfl_down_sync(FULL, h1, 4);
                        if (qrow == 0)
                            asm volatile("red.global.add.v2.f32 [%0], {%1,%2};"
                                         :: "l"(Hlo + col), "f"(h0), "f"(h1) : "memory");
                    }
                }
            }
        } else {
            const float* prh_base = g_Pr + (size_t)r_hi * OD;
            float* Hhi = g_H + (size_t)r_hi * OD;
            int rt;
            rt = __shfl_down_sync(FULL, r_lo, 4);  const bool s1l = (qrow < 7) && (rt == r_lo);
            rt = __shfl_down_sync(FULL, r_lo, 8);  const bool s2l = (qrow < 6) && (rt == r_lo);
            rt = __shfl_down_sync(FULL, r_lo, 16); const bool s4l = (qrow < 4) && (rt == r_lo);
            rt = __shfl_up_sync(FULL, r_lo, 4);    const bool hl  = (qrow == 0) || (rt != r_lo);
            rt = __shfl_down_sync(FULL, r_hi, 4);  const bool s1h = (qrow < 7) && (rt == r_hi);
            rt = __shfl_down_sync(FULL, r_hi, 8);  const bool s2h = (qrow < 6) && (rt == r_hi);
            rt = __shfl_down_sync(FULL, r_hi, 16); const bool s4h = (qrow < 4) && (rt == r_hi);
            rt = __shfl_up_sync(FULL, r_hi, 4);    const bool hh  = (qrow == 0) || (rt != r_hi);
#pragma unroll
            for (int g = 0; g < 4; g++) {
                float2 prl[4], prh[4], pcl[4], pch[4];
#pragma unroll
                for (int cc = 0; cc < 4; cc++) {
                    int col = (4 * g + cc) * 8 + qcol;
                    prl[cc] = *(const float2*)(prl_base + col);
                    prh[cc] = *(const float2*)(prh_base + col);
                    pcl[cc] = *(const float2*)(pcl_base + col);
                    pch[cc] = *(const float2*)(pch_base + col);
                }
#pragma unroll
                for (int t = 0; t < 2; t++) {
                    int n2 = 2 * g + t;
                    float a8[8];
#pragma unroll
                    for (int j = 0; j < 8; j++) a8[j] = 0.f;
#pragma unroll
                    for (int k = 0; k < 2; k++) {
                        uint32_t b[4];
                        ldmx4t(b, sb + E_W1 + k * 16 * PITCH_W_B + n2 * 32 + blane_off);
                        mma_f16(a8,     eh[k], b);
                        mma_f16(a8 + 4, eh[k], b + 2);
                    }
#pragma unroll
                    for (int u = 0; u < 2; u++) {
                        int cc = 2 * t + u;
                        int col = (4 * g + cc) * 8 + qcol;
                        float h0 = fmaxf(a8[u*4+0] + prl[cc].x + pcl[cc].x, 0.f);
                        float h1 = fmaxf(a8[u*4+1] + prl[cc].y + pcl[cc].y, 0.f);
                        float h2 = fmaxf(a8[u*4+2] + prh[cc].x + pch[cc].x, 0.f);
                        float h3 = fmaxf(a8[u*4+3] + prh[cc].y + pch[cc].y, 0.f);
                        if (!v_lo) { h0 = 0.f; h1 = 0.f; }
                        if (!v_hi) { h2 = 0.f; h3 = 0.f; }
                        float s;
                        s = __shfl_down_sync(FULL, h0, 4);  if (s1l) h0 += s;
                        s = __shfl_down_sync(FULL, h0, 8);  if (s2l) h0 += s;
                        s = __shfl_down_sync(FULL, h0, 16); if (s4l) h0 += s;
                        s = __shfl_down_sync(FULL, h1, 4);  if (s1l) h1 += s;
                        s = __shfl_down_sync(FULL, h1, 8);  if (s2l) h1 += s;
                        s = __shfl_down_sync(FULL, h1, 16); if (s4l) h1 += s;
                        s = __shfl_down_sync(FULL, h2, 4);  if (s1h) h2 += s;
                        s = __shfl_down_sync(FULL, h2, 8);  if (s2h) h2 += s;
                        s = __shfl_down_sync(FULL, h2, 16); if (s4h) h2 += s;
                        s = __shfl_down_sync(FULL, h3, 4);  if (s1h) h3 += s;
                        s = __shfl_down_sync(FULL, h3, 8);  if (s2h) h3 += s;
                        s = __shfl_down_sync(FULL, h3, 16); if (s4h) h3 += s;
                        if (hl)
                            asm volatile("red.global.add.v2.f32 [%0], {%1,%2};"
                                         :: "l"(Hlo + col), "f"(h0), "f"(h1) : "memory");
                        if (hh)
                            asm volatile("red.global.add.v2.f32 [%0], {%1,%2};"
                                         :: "l"(Hhi + col), "f"(h2), "f"(h3) : "memory");
                    }
                }
            }
        }

        // ---- store next tile into alternate buffer, single sync ----
        if (has_next) {
            if (tid < TE) {
                *(int*)(sm + nb2 + BUF_ROWS + tid * 4) = npk.x;
                *(int*)(sm + nb2 + BUF_COLS + tid * 4) = npk.y;
            }
            char* ph = sm + nb2 + BUF_EF + (tid >> 1) * PITCH_EF_B + ((tid & 1) * 16) * 2;
            *(uint4*)ph = nv0;
            *(uint4*)(ph + 16) = nv1;
        }
        __syncthreads();
    }
}

// ---------------------------------------------------------------------------
// Final: out = g_H @ W2 + deg * b2 (3-term split). 64-node blocks -> 157
// blocks cover all SMs (was 79 -> half the chip idle).
// Warp mapping: rows m0=(wid&3)*16, cols cbase=(wid>>2)*64 .. +63.
__global__ __launch_bounds__(256, 1) void final_out_mma_kernel(
    const float* __restrict__ b2g, float* __restrict__ out, int N) {
    extern __shared__ char sm[];
    const uint32_t sb = smem_u32(sm);
    const int tid = threadIdx.x;
    const int wid = tid >> 5;
    const int lane = tid & 31;
    const int l16 = lane & 15;
    const int qrow = lane >> 2;
    const int qcol = (lane & 3) * 2;
    const int n0 = blockIdx.x * 64;

    // stage H rows n0..n0+63 (fp32 -> hi/lo fp16)
    {
        int row = tid >> 2, c0 = (tid & 3) * 32;
        int node = n0 + row;
        char* ph = sm + G_AH + row * PITCH_W_B + c0 * 2;
        char* pl = sm + G_AL + row * PITCH_W_B + c0 * 2;
#pragma unroll
        for (int q = 0; q < 4; q++) {
            float4 f0 = make_float4(0.f, 0.f, 0.f, 0.f), f1 = f0;
            if (node < N) {
                f0 = *(const float4*)(g_H + (size_t)node * OD + c0 + q * 8);
                f1 = *(const float4*)(g_H + (size_t)node * OD + c0 + q * 8 + 4);
            }
            uint32_t h0, l0, h1, l1, h2, l2, h3, l3;
            split2h(f0.x, f0.y, h0, l0); split2h(f0.z, f0.w, h1, l1);
            split2h(f1.x, f1.y, h2, l2); split2h(f1.z, f1.w, h3, l3);
            *(uint4*)(ph + q * 16) = make_uint4(h0, h1, h2, h3);
            *(uint4*)(pl + q * 16) = make_uint4(l0, l1, l2, l3);
        }
    }
    for (int t = tid; t < 2048; t += 256) {
        int k = t >> 4, c8 = (t & 15) << 3;
        *(uint4*)(sm + G_WH + k * PITCH_W_B + c8 * 2) = *(const uint4*)(g_W2_hi + k * OD + c8);
        *(uint4*)(sm + G_WL + k * PITCH_W_B + c8 * 2) = *(const uint4*)(g_W2_lo + k * OD + c8);
    }
    if (tid < 128) ((float*)(sm + G_B2))[tid] = b2g[tid];
    if (tid < 64) {
        int node = n0 + tid;
        ((float*)(sm + G_DEG))[tid] = (node < N) ? (float)g_cnt[node] : 0.f;
    }
    __syncthreads();

    const int m0 = (wid & 3) * 16;
    const int cbase = (wid >> 2) * 64;
    uint32_t ahf[8][4], alf[8][4];
    {
        uint32_t ab_h = sb + G_AH + (m0 + l16) * PITCH_W_B + (lane >> 4) * 16;
        uint32_t ab_l = sb + G_AL + (m0 + l16) * PITCH_W_B + (lane >> 4) * 16;
#pragma unroll
        for (int k = 0; k < 8; k++) {
            ldmx4(ahf[k], ab_h + k * 32);
            ldmx4(alf[k], ab_l + k * 32);
        }
    }

    float acc[8][4];
#pragma unroll
    for (int i = 0; i < 8; i++)
#pragma unroll
        for (int j = 0; j < 4; j++) acc[i][j] = 0.f;
#pragma unroll
    for (int n2 = 0; n2 < 4; n2++) {
#pragma unroll
        for (int k = 0; k < 8; k++) {
            uint32_t bh[4], bl[4];
            uint32_t ba = (k * 16 + l16) * PITCH_W_B + (cbase + n2 * 16) * 2 + (lane >> 4) * 16;
            ldmx4t(bh, sb + G_WH + ba);
            ldmx4t(bl, sb + G_WL + ba);
            mma_f16(acc[2 * n2],     ahf[k], bh);
            mma_f16(acc[2 * n2],     ahf[k], bl);
            mma_f16(acc[2 * n2],     alf[k], bh);
            mma_f16(acc[2 * n2 + 1], ahf[k], bh + 2);
            mma_f16(acc[2 * n2 + 1], ahf[k], bl + 2);
            mma_f16(acc[2 * n2 + 1], alf[k], bh + 2);
        }
    }

    const int node_lo = n0 + m0 + qrow;
    const int node_hi = node_lo + 8;
    const float deg_lo = ((float*)(sm + G_DEG))[m0 + qrow];
    const float deg_hi = ((float*)(sm + G_DEG))[m0 + qrow + 8];
#pragma unroll
    for (int n2 = 0; n2 < 4; n2++) {
#pragma unroll
        for (int hlf = 0; hlf < 2; hlf++) {
            int col = cbase + n2 * 16 + hlf * 8 + qcol;
            float2 b2c = *(const float2*)(sm + G_B2 + col * 4);
            float* a = acc[2 * n2 + hlf];
            if (node_lo < N)
                *(float2*)(out + (size_t)node_lo * OD + col) =
                    make_float2(a[0] + deg_lo * b2c.x, a[1] + deg_lo * b2c.y);
            if (node_hi < N)
                *(float2*)(out + (size_t)node_hi * OD + col) =
                    make_float2(a[2] + deg_hi * b2c.x, a[3] + deg_hi * b2c.y);
        }
    }
}

// ---------------------------------------------------------------------------
extern "C" void kernel_launch(void* const* d_in, const int* in_sizes, int n_in,
                              void* d_out, int out_size) {
    const float* h = (const float*)d_in[0];
    const void* edge_index = d_in[1];
    const float* ef = (const float*)d_in[2];
    const float *W1 = 0, *b1 = 0, *W2 = 0, *b2 = 0;
    for (int i = 3; i < n_in; i++) {
        int s = in_sizes[i];
        if (s == (2 * ND + ED) * OD) W1 = (const float*)d_in[i];
        else if (s == OD * OD) W2 = (const float*)d_in[i];
        else if (s == OD) { if (!b1) b1 = (const float*)d_in[i]; else b2 = (const float*)d_in[i]; }
    }
    if (!W1 || !b1 || !W2 || !b2) return;

    int N = in_sizes[0] / ND;
    if (N > MAXN) N = MAXN;
    long long E = (long long)(in_sizes[1] / 2);
    if (E > MAXE) E = MAXE;
    float* out = (float*)d_out;
    int n_tiles = (int)((E + TE - 1) / TE);
    int nb = (N + 127) / 128;
    int nb64 = (N + 63) / 64;
    int eb = (int)((E + 255) / 256);

    static cudaStream_t s1 = 0, s2 = 0;
    static cudaEvent_t e0 = 0, e1 = 0, e2 = 0;
    if (!s1) {
        cudaStreamCreateWithFlags(&s1, cudaStreamNonBlocking);
        cudaStreamCreateWithFlags(&s2, cudaStreamNonBlocking);
        cudaEventCreateWithFlags(&e0, cudaEventDisableTiming);
        cudaEventCreateWithFlags(&e1, cudaEventDisableTiming);
        cudaEventCreateWithFlags(&e2, cudaEventDisableTiming);
    }

    // fork
    cudaEventRecord(e0, 0);
    cudaStreamWaitEvent(s1, e0, 0);
    cudaStreamWaitEvent(s2, e0, 0);

    // chain A (default): counting sort of edges by destination row
    zero_detect_kernel<<<(N + 255) / 256, 256>>>((const int*)edge_index, N);
    hist_kernel<<<eb * 2, 128>>>(edge_index, E);
    scan_kernel<<<1, 1024>>>(N);
    scatter_sort_kernel<<<(int)((E + 2047) / 2048), 256>>>(edge_index, E);

    // chain B (s1): weight prep + P precompute (+b1 baked into Pr)
    prep_weights_kernel<<<128, 256, 0, s1>>>(W1, W2);
    cudaFuncSetAttribute(precompute_P_mma_kernel,
                         cudaFuncAttributeMaxDynamicSharedMemorySize, F_TOTAL);
    {
        dim3 pgrid(nb, 2);
        precompute_P_mma_kernel<<<pgrid, 256, F_TOTAL, s1>>>(h, b1, N);
    }
    cudaEventRecord(e1, s1);

    // chain C (s2): ef fp16 preconvert + zero H
    convert_ef_kernel<<<(int)((E * 2 + 255) / 256), 256, 0, s2>>>(ef, E);
    zero_H_kernel<<<(N * OD + 255) / 256, 256, 0, s2>>>(N * OD);
    cudaEventRecord(e2, s2);

    // join
    cudaStreamWaitEvent(0, e1, 0);
    cudaStreamWaitEvent(0, e2, 0);

    int egrid = 3 * NSM;
    if (egrid > n_tiles) egrid = n_tiles;
    edge_hidden_kernel<<<egrid, 256, E_TOTAL>>>(E, n_tiles);

    cudaFuncSetAttribute(final_out_mma_kernel,
                         cudaFuncAttributeMaxDynamicSharedMemorySize, G_TOTAL);
    final_out_mma_kernel<<<nb64, 256, G_TOTAL>>>(b2, out, N);
}